// round 10
// baseline (speedup 1.0000x reference)
#include <cuda_runtime.h>
#include <cuda_bf16.h>
#include <cstdint>

#define DIM 128           // floats per row (512 B)
#define TILE 32           // entities per tile
#define DEPTH 2           // pipeline stages
#define SUB3_BLOCK 256    // 8 warps

// ---------------------------------------------------------------------------
// cp.async helpers (16B, L2 bypass-ish via evict_first policy)
// ---------------------------------------------------------------------------
__device__ __forceinline__ uint64_t make_evict_first_policy() {
    uint64_t pol;
    asm volatile("createpolicy.fractional.L2::evict_first.b64 %0, 1.0;" : "=l"(pol));
    return pol;
}
__device__ __forceinline__ void cpa16(uint32_t dst_smem, const void* src, uint64_t pol) {
    asm volatile("cp.async.cg.shared.global.L2::cache_hint [%0], [%1], 16, %2;"
                 :: "r"(dst_smem), "l"(src), "l"(pol));
}
__device__ __forceinline__ void cpa_commit() {
    asm volatile("cp.async.commit_group;");
}
template <int N>
__device__ __forceinline__ void cpa_wait() {
    asm volatile("cp.async.wait_group %0;" :: "n"(N));
}

// ---------------------------------------------------------------------------
// Kernel A (sub2): one block (256 thr = 8 warps) per type node c.
//   out[rc] = emb[rc] + sum_j emb[left_specific[sub2_row[...]]] + (n_ent-deg2)
// ---------------------------------------------------------------------------
__global__ void sub2_kernel(const float* __restrict__ emb,
                            const int* __restrict__ sub2_row,
                            const int* __restrict__ left_specific,
                            const int* __restrict__ right_common,
                            float* __restrict__ out,
                            int n_ent, int deg2) {
    extern __shared__ char smem_raw[];
    int*    rows = (int*)smem_raw;                                  // [deg2]
    float4* red  = (float4*)(smem_raw + ((deg2 * 4 + 127) & ~127)); // [8][32]

    const int c     = blockIdx.x;
    const int w     = threadIdx.x >> 5;
    const int lane  = threadIdx.x & 31;
    const int nwarp = blockDim.x >> 5;

    for (int j = threadIdx.x; j < deg2; j += blockDim.x)
        rows[j] = left_specific[__ldg(sub2_row + (size_t)c * deg2 + j)];
    __syncthreads();

    float4 acc = make_float4(0.f, 0.f, 0.f, 0.f);
    for (int j = w; j < deg2; j += nwarp) {
        const float4 v = __ldg((const float4*)(emb + (size_t)rows[j] * DIM) + lane);
        acc.x += v.x; acc.y += v.y; acc.z += v.z; acc.w += v.w;
    }
    red[w * 32 + lane] = acc;
    __syncthreads();

    if (w == 0) {
        float4 s = red[lane];
#pragma unroll
        for (int k = 1; k < 8; ++k) {
            const float4 v = red[k * 32 + lane];
            s.x += v.x; s.y += v.y; s.z += v.z; s.w += v.w;
        }
        const int   rc = right_common[c];
        const float a  = (float)(n_ent - deg2);
        const float4 e = __ldg((const float4*)(emb + (size_t)rc * DIM) + lane);
        float4 r;
        r.x = e.x + s.x + a; r.y = e.y + s.y + a;
        r.z = e.z + s.z + a; r.w = e.w + s.w + a;
        ((float4*)(out + (size_t)rc * DIM) + lane)[0] = r;
    }
}

// ---------------------------------------------------------------------------
// Kernel B (sub3, deg3==4): cp.async double-buffered SMEM pipeline.
// Per tile (32 entities): entity rows, sub3_row int4, right_specific staged
// into SMEM with evict_first L2 policy; compute does 4 L2 gathers of the
// (L2-resident) updated type rows + SMEM row read + __stcs write.
//   out[rs] = emb[rs] * (1 - (sum_j type_row + (n_typ-4)) / 5)
// ---------------------------------------------------------------------------
__global__ void __launch_bounds__(SUB3_BLOCK) sub3_pipe_d4(
        const float* __restrict__ emb,
        const int* __restrict__ sub3_row,
        const int* __restrict__ left_common,
        const int* __restrict__ right_specific,
        float* out,
        int n_ent, int n_typ, int ntiles) {
    __shared__ float4 srow[DEPTH][TILE][DIM / 4];   // 2*32*512B = 32 KB
    __shared__ int4   sidx[DEPTH][TILE];            // 1 KB
    __shared__ int    srs [DEPTH][TILE];            // 256 B

    const int tid  = threadIdx.x;
    const int w    = tid >> 5;
    const int lane = tid & 31;
    const uint64_t pol = make_evict_first_policy();

    // Prefetch one tile into slot `slot`.
    auto prefetch = [&](int tile, int slot) {
        if (tile < ntiles) {
            const int c0 = tile * TILE;
            // entity rows: thread -> row r = tid/8, segs (tid%8)*4 .. +3
            const int r = tid >> 3;
            const int c = c0 + r;
            if (c < n_ent) {
                const int rsv = __ldg(right_specific + c);
                const float4* g = (const float4*)(emb + (size_t)rsv * DIM);
                const int sb = (tid & 7) * 4;
                uint32_t d = (uint32_t)__cvta_generic_to_shared(&srow[slot][r][sb]);
#pragma unroll
                for (int s = 0; s < 4; ++s)
                    cpa16(d + 16u * s, g + sb + s, pol);
            }
            // indices (int4 per entity, exact-size elements)
            if (tid < TILE && c0 + tid < n_ent)
                cpa16((uint32_t)__cvta_generic_to_shared(&sidx[slot][tid]),
                      (const int4*)sub3_row + (c0 + tid), pol);
            // right_specific (only when the 16B quad is fully in range)
            if (tid < TILE / 4 && c0 + tid * 4 + 3 < n_ent)
                cpa16((uint32_t)__cvta_generic_to_shared(&srs[slot][tid * 4]),
                      right_specific + c0 + tid * 4, pol);
        }
        cpa_commit();   // uniform: every thread commits every group
    };

    const int stride = gridDim.x;
    const int t0 = blockIdx.x;

    // Prologue: fill the pipe.
    prefetch(t0, 0);
    prefetch(t0 + stride, 1);

    const float addc = (float)(n_typ - 4);
    const float inv  = 0.2f;

    int d = 0;
    for (int tile = t0; tile < ntiles; tile += stride, ++d) {
        const int slot = d & (DEPTH - 1);
        cpa_wait<DEPTH - 1>();
        __syncthreads();                      // stage `slot` visible to all

        const int c0 = tile * TILE;
        const bool full = (c0 + TILE <= n_ent);

        // Warp w handles entities k = w*4 .. w*4+3.
        int    rs[4];
        int4   idx[4];
        float4 acc[4];
#pragma unroll
        for (int i = 0; i < 4; ++i) {
            const int k = w * 4 + i;
            const int c = c0 + k;
            if (c < n_ent) {
                idx[i] = sidx[slot][k];
                rs[i]  = full ? srs[slot][k] : __ldg(right_specific + c);
            }
        }
#pragma unroll
        for (int i = 0; i < 4; ++i) acc[i] = make_float4(0.f, 0.f, 0.f, 0.f);
#pragma unroll
        for (int i = 0; i < 4; ++i) {
            const int c = c0 + w * 4 + i;
            if (c < n_ent) {
                const int f[4] = {idx[i].x, idx[i].y, idx[i].z, idx[i].w};
#pragma unroll
                for (int j = 0; j < 4; ++j) {
                    const int node = __ldg(left_common + f[j]);
                    const float4 v = __ldg((const float4*)(out + (size_t)node * DIM) + lane);
                    acc[i].x += v.x; acc[i].y += v.y; acc[i].z += v.z; acc[i].w += v.w;
                }
            }
        }
#pragma unroll
        for (int i = 0; i < 4; ++i) {
            const int k = w * 4 + i;
            const int c = c0 + k;
            if (c < n_ent) {
                const float4 e = srow[slot][k][lane];
                float4 o;
                o.x = e.x * (1.0f - (acc[i].x + addc) * inv);
                o.y = e.y * (1.0f - (acc[i].y + addc) * inv);
                o.z = e.z * (1.0f - (acc[i].z + addc) * inv);
                o.w = e.w * (1.0f - (acc[i].w + addc) * inv);
                __stcs((float4*)(out + (size_t)rs[i] * DIM) + lane, o);
            }
        }

        __syncthreads();                      // all reads of `slot` done
        prefetch(tile + DEPTH * stride, slot);
    }
}

// Generic fallback (any deg3), one warp per entity.
__global__ void sub3_kernel_gen(const float* __restrict__ emb,
                                const int* __restrict__ sub3_row,
                                const int* __restrict__ left_common,
                                const int* __restrict__ right_specific,
                                float* out,
                                int n_ent, int n_typ, int deg3) {
    const int gw   = (int)((blockIdx.x * (size_t)blockDim.x + threadIdx.x) >> 5);
    const int lane = threadIdx.x & 31;
    if (gw >= n_ent) return;

    const float addc = (float)(n_typ - deg3);
    const float inv  = 1.0f / (float)(1 + deg3);

    float4 acc = make_float4(0.f, 0.f, 0.f, 0.f);
    const int* rbase = sub3_row + (size_t)gw * deg3;
    for (int j = 0; j < deg3; ++j) {
        const int node = left_common[__ldg(rbase + j)];
        const float4 v = __ldg((const float4*)(out + (size_t)node * DIM) + lane);
        acc.x += v.x; acc.y += v.y; acc.z += v.z; acc.w += v.w;
    }
    const int   rs = right_specific[gw];
    const float4 e = __ldcs((const float4*)(emb + (size_t)rs * DIM) + lane);
    float4 r;
    r.x = e.x * (1.0f - (acc.x + addc) * inv);
    r.y = e.y * (1.0f - (acc.y + addc) * inv);
    r.z = e.z * (1.0f - (acc.z + addc) * inv);
    r.w = e.w * (1.0f - (acc.w + addc) * inv);
    __stcs((float4*)(out + (size_t)rs * DIM) + lane, r);
}

extern "C" void kernel_launch(void* const* d_in, const int* in_sizes, int n_in,
                              void* d_out, int out_size) {
    const float* emb            = (const float*)d_in[0];
    const int*   sub2_row       = (const int*)d_in[1];
    const int*   sub3_row       = (const int*)d_in[3];
    const int*   left_specific  = (const int*)d_in[5];
    const int*   right_common   = (const int*)d_in[6];
    const int*   left_common    = (const int*)d_in[7];
    const int*   right_specific = (const int*)d_in[8];
    float*       out            = (float*)d_out;

    const int n_ent = in_sizes[5];                 // 200000
    const int n_typ = in_sizes[7];                 // 1000
    const int deg2  = in_sizes[1] / n_typ;         // 64
    const int deg3  = in_sizes[3] / n_ent;         // 4

    // Phase 1: updated type rows -> out[type rows]
    const int smem = ((deg2 * 4 + 127) & ~127) + 8 * 32 * (int)sizeof(float4);
    sub2_kernel<<<n_typ, 256, smem>>>(
        emb, sub2_row, left_specific, right_common, out, n_ent, deg2);

    // Phase 2: updated entity rows (stream-ordered after sub2).
    if (deg3 == 4) {
        const int ntiles = (n_ent + TILE - 1) / TILE;
        int blocks = 148 * 6;                      // ~6 blocks/SM (34KB smem each)
        if (blocks > ntiles) blocks = ntiles;
        sub3_pipe_d4<<<blocks, SUB3_BLOCK>>>(
            emb, sub3_row, left_common, right_specific, out, n_ent, n_typ, ntiles);
    } else {
        const int wpb = 8;
        const int blocks = (n_ent + wpb - 1) / wpb;
        sub3_kernel_gen<<<blocks, wpb * 32>>>(
            emb, sub3_row, left_common, right_specific, out, n_ent, n_typ, deg3);
    }
}

// round 11
// speedup vs baseline: 1.6706x; 1.6706x over previous
#include <cuda_runtime.h>
#include <cuda_bf16.h>

#define DIM 128

// ---------------------------------------------------------------------------
// Kernel A (sub2): one block (256 thr = 8 warps) per type node c.
//   out[rc] = emb[rc] + sum_j emb[left_specific[sub2_row[...]]] + (n_ent-deg2)
// ---------------------------------------------------------------------------
__global__ void sub2_kernel(const float* __restrict__ emb,
                            const int* __restrict__ sub2_row,
                            const int* __restrict__ left_specific,
                            const int* __restrict__ right_common,
                            float* __restrict__ out,
                            int n_ent, int deg2) {
    extern __shared__ char smem_raw[];
    int*    rows = (int*)smem_raw;                                  // [deg2]
    float4* red  = (float4*)(smem_raw + ((deg2 * 4 + 127) & ~127)); // [8][32]

    const int c     = blockIdx.x;
    const int w     = threadIdx.x >> 5;
    const int lane  = threadIdx.x & 31;
    const int nwarp = blockDim.x >> 5;

    for (int j = threadIdx.x; j < deg2; j += blockDim.x)
        rows[j] = left_specific[__ldg(sub2_row + (size_t)c * deg2 + j)];
    __syncthreads();

    float4 acc = make_float4(0.f, 0.f, 0.f, 0.f);
    for (int j = w; j < deg2; j += nwarp) {
        const float4 v = __ldg((const float4*)(emb + (size_t)rows[j] * DIM) + lane);
        acc.x += v.x; acc.y += v.y; acc.z += v.z; acc.w += v.w;
    }
    red[w * 32 + lane] = acc;
    __syncthreads();

    if (w == 0) {
        float4 s = red[lane];
#pragma unroll
        for (int k = 1; k < 8; ++k) {
            const float4 v = red[k * 32 + lane];
            s.x += v.x; s.y += v.y; s.z += v.z; s.w += v.w;
        }
        const int   rc = right_common[c];
        const float a  = (float)(n_ent - deg2);
        const float4 e = __ldg((const float4*)(emb + (size_t)rc * DIM) + lane);
        float4 r;
        r.x = e.x + s.x + a; r.y = e.y + s.y + a;
        r.z = e.z + s.z + a; r.w = e.w + s.w + a;
        ((float4*)(out + (size_t)rc * DIM) + lane)[0] = r;
    }
}

// ---------------------------------------------------------------------------
// Kernel B (sub3, deg3==4): 2 entities per warp, register-lean so 8 blocks
// resident per SM (__launch_bounds__(256,8) -> <=32 regs). Front-batched
// loads: 2 streaming entity rows (__ldcs, evict-first: R8 proved keeping emb
// resident thrashes L2) + 8 independent L2 gathers of the updated type rows.
//   out[rs] = emb[rs] * (1 - (sum_j type_row + (n_typ-4)) / 5)
// ---------------------------------------------------------------------------
__global__ void __launch_bounds__(256, 8) sub3_kernel_d2(
        const float* __restrict__ emb,
        const int* __restrict__ sub3_row,
        const int* __restrict__ left_common,
        const int* __restrict__ right_specific,
        float* out,
        int n_ent, int n_typ) {
    const int gw   = blockIdx.x * 8 + (threadIdx.x >> 5);
    const int lane = threadIdx.x & 31;
    const int base = gw * 2;
    if (base >= n_ent) return;
    const bool two = (base + 1 < n_ent);

    // lanes 0-7: type node ids (4 per entity); lanes 8-9: entity row ids.
    int node_l = 0;
    if (lane < 8 && base + (lane >> 2) < n_ent)
        node_l = __ldg(left_common + __ldg(sub3_row + (size_t)base * 4 + lane));
    int rs_l = 0;
    if (lane >= 8 && lane < 10 && base + (lane - 8) < n_ent)
        rs_l = __ldg(right_specific + base + (lane - 8));

    const int rs0 = __shfl_sync(0xffffffffu, rs_l, 8);
    const int rs1 = __shfl_sync(0xffffffffu, rs_l, 9);

    // Streaming entity loads first (DRAM, longest latency).
    float4 e0 = __ldcs((const float4*)(emb + (size_t)rs0 * DIM) + lane);
    float4 e1 = make_float4(0.f, 0.f, 0.f, 0.f);
    if (two)
        e1 = __ldcs((const float4*)(emb + (size_t)rs1 * DIM) + lane);

    // 8 independent gathers of L2-resident updated type rows.
    float4 a0 = make_float4(0.f, 0.f, 0.f, 0.f);
    float4 a1 = make_float4(0.f, 0.f, 0.f, 0.f);
#pragma unroll
    for (int j = 0; j < 4; ++j) {
        const int n0 = __shfl_sync(0xffffffffu, node_l, j);
        const float4 v = __ldg((const float4*)(out + (size_t)n0 * DIM) + lane);
        a0.x += v.x; a0.y += v.y; a0.z += v.z; a0.w += v.w;
    }
    if (two) {
#pragma unroll
        for (int j = 4; j < 8; ++j) {
            const int n1 = __shfl_sync(0xffffffffu, node_l, j);
            const float4 v = __ldg((const float4*)(out + (size_t)n1 * DIM) + lane);
            a1.x += v.x; a1.y += v.y; a1.z += v.z; a1.w += v.w;
        }
    }

    const float addc = (float)(n_typ - 4);
    const float inv  = 0.2f;

    float4 o0;
    o0.x = e0.x * (1.0f - (a0.x + addc) * inv);
    o0.y = e0.y * (1.0f - (a0.y + addc) * inv);
    o0.z = e0.z * (1.0f - (a0.z + addc) * inv);
    o0.w = e0.w * (1.0f - (a0.w + addc) * inv);
    __stcs((float4*)(out + (size_t)rs0 * DIM) + lane, o0);

    if (two) {
        float4 o1;
        o1.x = e1.x * (1.0f - (a1.x + addc) * inv);
        o1.y = e1.y * (1.0f - (a1.y + addc) * inv);
        o1.z = e1.z * (1.0f - (a1.z + addc) * inv);
        o1.w = e1.w * (1.0f - (a1.w + addc) * inv);
        __stcs((float4*)(out + (size_t)rs1 * DIM) + lane, o1);
    }
}

// Generic fallback (any deg3), one warp per entity.
__global__ void sub3_kernel_gen(const float* __restrict__ emb,
                                const int* __restrict__ sub3_row,
                                const int* __restrict__ left_common,
                                const int* __restrict__ right_specific,
                                float* out,
                                int n_ent, int n_typ, int deg3) {
    const int gw   = (int)((blockIdx.x * (size_t)blockDim.x + threadIdx.x) >> 5);
    const int lane = threadIdx.x & 31;
    if (gw >= n_ent) return;

    const float addc = (float)(n_typ - deg3);
    const float inv  = 1.0f / (float)(1 + deg3);

    float4 acc = make_float4(0.f, 0.f, 0.f, 0.f);
    const int* rbase = sub3_row + (size_t)gw * deg3;
    for (int j = 0; j < deg3; ++j) {
        const int node = left_common[__ldg(rbase + j)];
        const float4 v = __ldg((const float4*)(out + (size_t)node * DIM) + lane);
        acc.x += v.x; acc.y += v.y; acc.z += v.z; acc.w += v.w;
    }
    const int   rs = right_specific[gw];
    const float4 e = __ldcs((const float4*)(emb + (size_t)rs * DIM) + lane);
    float4 r;
    r.x = e.x * (1.0f - (acc.x + addc) * inv);
    r.y = e.y * (1.0f - (acc.y + addc) * inv);
    r.z = e.z * (1.0f - (acc.z + addc) * inv);
    r.w = e.w * (1.0f - (acc.w + addc) * inv);
    __stcs((float4*)(out + (size_t)rs * DIM) + lane, r);
}

extern "C" void kernel_launch(void* const* d_in, const int* in_sizes, int n_in,
                              void* d_out, int out_size) {
    const float* emb            = (const float*)d_in[0];
    const int*   sub2_row       = (const int*)d_in[1];
    const int*   sub3_row       = (const int*)d_in[3];
    const int*   left_specific  = (const int*)d_in[5];
    const int*   right_common   = (const int*)d_in[6];
    const int*   left_common    = (const int*)d_in[7];
    const int*   right_specific = (const int*)d_in[8];
    float*       out            = (float*)d_out;

    const int n_ent = in_sizes[5];                 // 200000
    const int n_typ = in_sizes[7];                 // 1000
    const int deg2  = in_sizes[1] / n_typ;         // 64
    const int deg3  = in_sizes[3] / n_ent;         // 4

    // Phase 1: updated type rows -> out[type rows]
    const int smem = ((deg2 * 4 + 127) & ~127) + 8 * 32 * (int)sizeof(float4);
    sub2_kernel<<<n_typ, 256, smem>>>(
        emb, sub2_row, left_specific, right_common, out, n_ent, deg2);

    // Phase 2: updated entity rows -> out[entity rows]
    if (deg3 == 4) {
        const int ent_per_block = 8 * 2;           // 8 warps x 2 entities
        const int blocks = (n_ent + ent_per_block - 1) / ent_per_block;
        sub3_kernel_d2<<<blocks, 256>>>(
            emb, sub3_row, left_common, right_specific, out, n_ent, n_typ);
    } else {
        const int wpb = 8;
        const int blocks = (n_ent + wpb - 1) / wpb;
        sub3_kernel_gen<<<blocks, wpb * 32>>>(
            emb, sub3_row, left_common, right_specific, out, n_ent, n_typ, deg3);
    }
}

// round 12
// speedup vs baseline: 1.7492x; 1.0471x over previous
#include <cuda_runtime.h>
#include <cuda_bf16.h>

#define DIM 128
#define MAX_TYP 4096

// Window sums of updated type rows: W[t] = sum_{j<4} out[left_common[(t+j)%n_typ]]
__device__ float g_W[MAX_TYP * DIM];   // 2 MB static scratch

// ---------------------------------------------------------------------------
// Kernel A (sub2): one block (256 thr = 8 warps) per type node c.
//   out[rc] = emb[rc] + sum_j emb[left_specific[sub2_row[...]]] + (n_ent-deg2)
// ---------------------------------------------------------------------------
__global__ void sub2_kernel(const float* __restrict__ emb,
                            const int* __restrict__ sub2_row,
                            const int* __restrict__ left_specific,
                            const int* __restrict__ right_common,
                            float* __restrict__ out,
                            int n_ent, int deg2) {
    extern __shared__ char smem_raw[];
    int*    rows = (int*)smem_raw;                                  // [deg2]
    float4* red  = (float4*)(smem_raw + ((deg2 * 4 + 127) & ~127)); // [8][32]

    const int c     = blockIdx.x;
    const int w     = threadIdx.x >> 5;
    const int lane  = threadIdx.x & 31;
    const int nwarp = blockDim.x >> 5;

    for (int j = threadIdx.x; j < deg2; j += blockDim.x)
        rows[j] = left_specific[__ldg(sub2_row + (size_t)c * deg2 + j)];
    __syncthreads();

    float4 acc = make_float4(0.f, 0.f, 0.f, 0.f);
    for (int j = w; j < deg2; j += nwarp) {
        const float4 v = __ldg((const float4*)(emb + (size_t)rows[j] * DIM) + lane);
        acc.x += v.x; acc.y += v.y; acc.z += v.z; acc.w += v.w;
    }
    red[w * 32 + lane] = acc;
    __syncthreads();

    if (w == 0) {
        float4 s = red[lane];
#pragma unroll
        for (int k = 1; k < 8; ++k) {
            const float4 v = red[k * 32 + lane];
            s.x += v.x; s.y += v.y; s.z += v.z; s.w += v.w;
        }
        const int   rc = right_common[c];
        const float a  = (float)(n_ent - deg2);
        const float4 e = __ldg((const float4*)(emb + (size_t)rc * DIM) + lane);
        float4 r;
        r.x = e.x + s.x + a; r.y = e.y + s.y + a;
        r.z = e.z + s.z + a; r.w = e.w + s.w + a;
        ((float4*)(out + (size_t)rc * DIM) + lane)[0] = r;
    }
}

// ---------------------------------------------------------------------------
// Window precompute (deg3==4): one warp per window start t, 4 warps/block.
// Reads the 1000 updated (L2-resident) type rows, writes W.
// ---------------------------------------------------------------------------
__global__ void window_kernel(const float* __restrict__ out,
                              const int* __restrict__ left_common,
                              int n_typ) {
    const int t    = blockIdx.x * (blockDim.x >> 5) + (threadIdx.x >> 5);
    const int lane = threadIdx.x & 31;
    if (t >= n_typ) return;
    float4 acc = make_float4(0.f, 0.f, 0.f, 0.f);
#pragma unroll
    for (int j = 0; j < 4; ++j) {
        int tt = t + j;
        if (tt >= n_typ) tt -= n_typ;
        const int node = __ldg(left_common + tt);
        const float4 v = __ldg((const float4*)(out + (size_t)node * DIM) + lane);
        acc.x += v.x; acc.y += v.y; acc.z += v.z; acc.w += v.w;
    }
    ((float4*)(g_W + (size_t)t * DIM))[lane] = acc;
}

// ---------------------------------------------------------------------------
// Kernel B (sub3, deg3==4): 2 entities per warp, register-lean
// (__launch_bounds__(256,8)). Per entity: verify (via shuffles) that its 4
// indices form the window (b, b+1, b+2, b+3) mod n_typ; if so ONE gather of
// W[b] replaces 4 type-row gathers. Warp-uniform fallback does direct
// gathers. Entity stream stays __ldcs/__stcs (R8: must evict-first).
//   out[rs] = emb[rs] * (1 - (sum + (n_typ-4)) / 5)
// ---------------------------------------------------------------------------
__global__ void __launch_bounds__(256, 8) sub3_kernel_d2w(
        const float* __restrict__ emb,
        const int* __restrict__ sub3_row,
        const int* __restrict__ left_common,
        const int* __restrict__ right_specific,
        float* out,
        int n_ent, int n_typ) {
    const int gw   = blockIdx.x * 8 + (threadIdx.x >> 5);
    const int lane = threadIdx.x & 31;
    const int base = gw * 2;
    if (base >= n_ent) return;
    const bool two = (base + 1 < n_ent);

    // lanes 0-7: raw sub3 indices (4 per entity); lanes 8-9: entity row ids.
    int ridx_l = 0;
    if (lane < 8 && base + (lane >> 2) < n_ent)
        ridx_l = __ldg(sub3_row + (size_t)base * 4 + lane);
    int rs_l = 0;
    if (lane >= 8 && lane < 10 && base + (lane - 8) < n_ent)
        rs_l = __ldg(right_specific + base + (lane - 8));

    const int rs0 = __shfl_sync(0xffffffffu, rs_l, 8);
    const int rs1 = __shfl_sync(0xffffffffu, rs_l, 9);

    // Streaming entity loads first (DRAM, longest latency).
    float4 e0 = __ldcs((const float4*)(emb + (size_t)rs0 * DIM) + lane);
    float4 e1 = make_float4(0.f, 0.f, 0.f, 0.f);
    if (two)
        e1 = __ldcs((const float4*)(emb + (size_t)rs1 * DIM) + lane);

    // Window verification (all-lane shuffles -> warp-uniform predicates).
    const int b0 = __shfl_sync(0xffffffffu, ridx_l, 0);
    const int b1 = __shfl_sync(0xffffffffu, ridx_l, 4);
    bool ok0 = (b0 >= 0) && (b0 < n_typ);
    bool ok1 = (b1 >= 0) && (b1 < n_typ);
#pragma unroll
    for (int j = 1; j < 4; ++j) {
        int x0 = b0 + j; if (x0 >= n_typ) x0 -= n_typ;
        int x1 = b1 + j; if (x1 >= n_typ) x1 -= n_typ;
        ok0 = ok0 && (__shfl_sync(0xffffffffu, ridx_l, j)     == x0);
        ok1 = ok1 && (__shfl_sync(0xffffffffu, ridx_l, 4 + j) == x1);
    }

    float4 a0, a1;
    if (ok0) {
        a0 = ((const float4*)(g_W + (size_t)b0 * DIM))[lane];
    } else {
        a0 = make_float4(0.f, 0.f, 0.f, 0.f);
#pragma unroll
        for (int j = 0; j < 4; ++j) {
            const int node = __ldg(left_common + __shfl_sync(0xffffffffu, ridx_l, j));
            const float4 v = __ldg((const float4*)(out + (size_t)node * DIM) + lane);
            a0.x += v.x; a0.y += v.y; a0.z += v.z; a0.w += v.w;
        }
    }
    if (two) {
        if (ok1) {
            a1 = ((const float4*)(g_W + (size_t)b1 * DIM))[lane];
        } else {
            a1 = make_float4(0.f, 0.f, 0.f, 0.f);
#pragma unroll
            for (int j = 0; j < 4; ++j) {
                const int node = __ldg(left_common + __shfl_sync(0xffffffffu, ridx_l, 4 + j));
                const float4 v = __ldg((const float4*)(out + (size_t)node * DIM) + lane);
                a1.x += v.x; a1.y += v.y; a1.z += v.z; a1.w += v.w;
            }
        }
    }

    const float addc = (float)(n_typ - 4);
    const float inv  = 0.2f;

    float4 o0;
    o0.x = e0.x * (1.0f - (a0.x + addc) * inv);
    o0.y = e0.y * (1.0f - (a0.y + addc) * inv);
    o0.z = e0.z * (1.0f - (a0.z + addc) * inv);
    o0.w = e0.w * (1.0f - (a0.w + addc) * inv);
    __stcs((float4*)(out + (size_t)rs0 * DIM) + lane, o0);

    if (two) {
        float4 o1;
        o1.x = e1.x * (1.0f - (a1.x + addc) * inv);
        o1.y = e1.y * (1.0f - (a1.y + addc) * inv);
        o1.z = e1.z * (1.0f - (a1.z + addc) * inv);
        o1.w = e1.w * (1.0f - (a1.w + addc) * inv);
        __stcs((float4*)(out + (size_t)rs1 * DIM) + lane, o1);
    }
}

// Generic fallback (any deg3), one warp per entity.
__global__ void sub3_kernel_gen(const float* __restrict__ emb,
                                const int* __restrict__ sub3_row,
                                const int* __restrict__ left_common,
                                const int* __restrict__ right_specific,
                                float* out,
                                int n_ent, int n_typ, int deg3) {
    const int gw   = (int)((blockIdx.x * (size_t)blockDim.x + threadIdx.x) >> 5);
    const int lane = threadIdx.x & 31;
    if (gw >= n_ent) return;

    const float addc = (float)(n_typ - deg3);
    const float inv  = 1.0f / (float)(1 + deg3);

    float4 acc = make_float4(0.f, 0.f, 0.f, 0.f);
    const int* rbase = sub3_row + (size_t)gw * deg3;
    for (int j = 0; j < deg3; ++j) {
        const int node = left_common[__ldg(rbase + j)];
        const float4 v = __ldg((const float4*)(out + (size_t)node * DIM) + lane);
        acc.x += v.x; acc.y += v.y; acc.z += v.z; acc.w += v.w;
    }
    const int   rs = right_specific[gw];
    const float4 e = __ldcs((const float4*)(emb + (size_t)rs * DIM) + lane);
    float4 r;
    r.x = e.x * (1.0f - (acc.x + addc) * inv);
    r.y = e.y * (1.0f - (acc.y + addc) * inv);
    r.z = e.z * (1.0f - (acc.z + addc) * inv);
    r.w = e.w * (1.0f - (acc.w + addc) * inv);
    __stcs((float4*)(out + (size_t)rs * DIM) + lane, r);
}

extern "C" void kernel_launch(void* const* d_in, const int* in_sizes, int n_in,
                              void* d_out, int out_size) {
    const float* emb            = (const float*)d_in[0];
    const int*   sub2_row       = (const int*)d_in[1];
    const int*   sub3_row       = (const int*)d_in[3];
    const int*   left_specific  = (const int*)d_in[5];
    const int*   right_common   = (const int*)d_in[6];
    const int*   left_common    = (const int*)d_in[7];
    const int*   right_specific = (const int*)d_in[8];
    float*       out            = (float*)d_out;

    const int n_ent = in_sizes[5];                 // 200000
    const int n_typ = in_sizes[7];                 // 1000
    const int deg2  = in_sizes[1] / n_typ;         // 64
    const int deg3  = in_sizes[3] / n_ent;         // 4

    // Phase 1: updated type rows -> out[type rows]
    const int smem = ((deg2 * 4 + 127) & ~127) + 8 * 32 * (int)sizeof(float4);
    sub2_kernel<<<n_typ, 256, smem>>>(
        emb, sub2_row, left_specific, right_common, out, n_ent, deg2);

    if (deg3 == 4 && n_typ <= MAX_TYP) {
        // Window sums over updated type rows (stream-ordered after sub2).
        window_kernel<<<(n_typ + 3) / 4, 128>>>(out, left_common, n_typ);
        // Phase 2: high-occupancy d2 kernel, 1 gather per entity.
        const int ent_per_block = 8 * 2;
        const int blocks = (n_ent + ent_per_block - 1) / ent_per_block;
        sub3_kernel_d2w<<<blocks, 256>>>(
            emb, sub3_row, left_common, right_specific, out, n_ent, n_typ);
    } else {
        const int wpb = 8;
        const int blocks = (n_ent + wpb - 1) / wpb;
        sub3_kernel_gen<<<blocks, wpb * 32>>>(
            emb, sub3_row, left_common, right_specific, out, n_ent, n_typ, deg3);
    }
}

// round 13
// speedup vs baseline: 1.8401x; 1.0519x over previous
#include <cuda_runtime.h>
#include <cuda_bf16.h>

#define DIM 128
#define MAX_TYP 4096

// Window sums of updated type rows: W[t] = sum_{j<4} out[left_common[(t+j)%n_typ]]
__device__ float g_W[MAX_TYP * DIM];   // 2 MB static scratch

// ---------------------------------------------------------------------------
// Kernel A (sub2), specialized deg2 % 8 == 0: one block (8 warps) per type c.
// Warp w owns edges [c*deg2 + w*8, +8): lanes 0-7 resolve the 8 row indices
// (2-deep chain, 8 in parallel), shuffle-broadcast, then 8 UNROLLED
// independent float4 row loads front-batched before the accumulate.
//   out[rc] = emb[rc] + sum_j emb[left_specific[sub2_row[...]]] + (n_ent-deg2)
// ---------------------------------------------------------------------------
__global__ void __launch_bounds__(256, 8) sub2_kernel_u8(
        const float* __restrict__ emb,
        const int* __restrict__ sub2_row,
        const int* __restrict__ left_specific,
        const int* __restrict__ right_common,
        float* __restrict__ out,
        int n_ent, int deg2) {
    __shared__ float4 red[8][32];

    const int c    = blockIdx.x;
    const int w    = threadIdx.x >> 5;
    const int lane = threadIdx.x & 31;

    // Lanes 0-7: resolve this warp's 8 row indices.
    int row_l = 0;
    if (lane < 8)
        row_l = __ldg(left_specific + __ldg(sub2_row + (size_t)c * deg2 + w * 8 + lane));

    int rows[8];
#pragma unroll
    for (int i = 0; i < 8; ++i)
        rows[i] = __shfl_sync(0xffffffffu, row_l, i);

    // 8 independent row loads, front-batched.
    float4 v[8];
#pragma unroll
    for (int i = 0; i < 8; ++i)
        v[i] = __ldg((const float4*)(emb + (size_t)rows[i] * DIM) + lane);

    float4 acc = v[0];
#pragma unroll
    for (int i = 1; i < 8; ++i) {
        acc.x += v[i].x; acc.y += v[i].y; acc.z += v[i].z; acc.w += v[i].w;
    }
    red[w][lane] = acc;
    __syncthreads();

    if (w == 0) {
        float4 s = red[0][lane];
#pragma unroll
        for (int k = 1; k < 8; ++k) {
            const float4 t = red[k][lane];
            s.x += t.x; s.y += t.y; s.z += t.z; s.w += t.w;
        }
        const int   rc = __ldg(right_common + c);
        const float a  = (float)(n_ent - deg2);
        const float4 e = __ldg((const float4*)(emb + (size_t)rc * DIM) + lane);
        float4 r;
        r.x = e.x + s.x + a; r.y = e.y + s.y + a;
        r.z = e.z + s.z + a; r.w = e.w + s.w + a;
        ((float4*)(out + (size_t)rc * DIM))[lane] = r;
    }
}

// Generic sub2 (any deg2): prior working version.
__global__ void sub2_kernel(const float* __restrict__ emb,
                            const int* __restrict__ sub2_row,
                            const int* __restrict__ left_specific,
                            const int* __restrict__ right_common,
                            float* __restrict__ out,
                            int n_ent, int deg2) {
    extern __shared__ char smem_raw[];
    int*    rows = (int*)smem_raw;                                  // [deg2]
    float4* red  = (float4*)(smem_raw + ((deg2 * 4 + 127) & ~127)); // [8][32]

    const int c     = blockIdx.x;
    const int w     = threadIdx.x >> 5;
    const int lane  = threadIdx.x & 31;
    const int nwarp = blockDim.x >> 5;

    for (int j = threadIdx.x; j < deg2; j += blockDim.x)
        rows[j] = left_specific[__ldg(sub2_row + (size_t)c * deg2 + j)];
    __syncthreads();

    float4 acc = make_float4(0.f, 0.f, 0.f, 0.f);
    for (int j = w; j < deg2; j += nwarp) {
        const float4 v = __ldg((const float4*)(emb + (size_t)rows[j] * DIM) + lane);
        acc.x += v.x; acc.y += v.y; acc.z += v.z; acc.w += v.w;
    }
    red[w * 32 + lane] = acc;
    __syncthreads();

    if (w == 0) {
        float4 s = red[lane];
#pragma unroll
        for (int k = 1; k < 8; ++k) {
            const float4 v = red[k * 32 + lane];
            s.x += v.x; s.y += v.y; s.z += v.z; s.w += v.w;
        }
        const int   rc = right_common[c];
        const float a  = (float)(n_ent - deg2);
        const float4 e = __ldg((const float4*)(emb + (size_t)rc * DIM) + lane);
        float4 r;
        r.x = e.x + s.x + a; r.y = e.y + s.y + a;
        r.z = e.z + s.z + a; r.w = e.w + s.w + a;
        ((float4*)(out + (size_t)rc * DIM) + lane)[0] = r;
    }
}

// ---------------------------------------------------------------------------
// Window precompute (deg3==4): one warp per window start t, 4 warps/block.
// ---------------------------------------------------------------------------
__global__ void window_kernel(const float* __restrict__ out,
                              const int* __restrict__ left_common,
                              int n_typ) {
    const int t    = blockIdx.x * (blockDim.x >> 5) + (threadIdx.x >> 5);
    const int lane = threadIdx.x & 31;
    if (t >= n_typ) return;
    float4 acc = make_float4(0.f, 0.f, 0.f, 0.f);
#pragma unroll
    for (int j = 0; j < 4; ++j) {
        int tt = t + j;
        if (tt >= n_typ) tt -= n_typ;
        const int node = __ldg(left_common + tt);
        const float4 v = __ldg((const float4*)(out + (size_t)node * DIM) + lane);
        acc.x += v.x; acc.y += v.y; acc.z += v.z; acc.w += v.w;
    }
    ((float4*)(g_W + (size_t)t * DIM))[lane] = acc;
}

// ---------------------------------------------------------------------------
// Kernel B (sub3, deg3==4): 2 entities/warp, register-lean (256,8). Window
// verification via shuffles; 1 W-gather per entity, gather fallback if the
// indices aren't a consecutive window. Entity stream __ldcs/__stcs.
// ---------------------------------------------------------------------------
__global__ void __launch_bounds__(256, 8) sub3_kernel_d2w(
        const float* __restrict__ emb,
        const int* __restrict__ sub3_row,
        const int* __restrict__ left_common,
        const int* __restrict__ right_specific,
        float* out,
        int n_ent, int n_typ) {
    const int gw   = blockIdx.x * 8 + (threadIdx.x >> 5);
    const int lane = threadIdx.x & 31;
    const int base = gw * 2;
    if (base >= n_ent) return;
    const bool two = (base + 1 < n_ent);

    int ridx_l = 0;
    if (lane < 8 && base + (lane >> 2) < n_ent)
        ridx_l = __ldg(sub3_row + (size_t)base * 4 + lane);
    int rs_l = 0;
    if (lane >= 8 && lane < 10 && base + (lane - 8) < n_ent)
        rs_l = __ldg(right_specific + base + (lane - 8));

    const int rs0 = __shfl_sync(0xffffffffu, rs_l, 8);
    const int rs1 = __shfl_sync(0xffffffffu, rs_l, 9);

    float4 e0 = __ldcs((const float4*)(emb + (size_t)rs0 * DIM) + lane);
    float4 e1 = make_float4(0.f, 0.f, 0.f, 0.f);
    if (two)
        e1 = __ldcs((const float4*)(emb + (size_t)rs1 * DIM) + lane);

    const int b0 = __shfl_sync(0xffffffffu, ridx_l, 0);
    const int b1 = __shfl_sync(0xffffffffu, ridx_l, 4);
    bool ok0 = (b0 >= 0) && (b0 < n_typ);
    bool ok1 = (b1 >= 0) && (b1 < n_typ);
#pragma unroll
    for (int j = 1; j < 4; ++j) {
        int x0 = b0 + j; if (x0 >= n_typ) x0 -= n_typ;
        int x1 = b1 + j; if (x1 >= n_typ) x1 -= n_typ;
        ok0 = ok0 && (__shfl_sync(0xffffffffu, ridx_l, j)     == x0);
        ok1 = ok1 && (__shfl_sync(0xffffffffu, ridx_l, 4 + j) == x1);
    }

    float4 a0, a1;
    if (ok0) {
        a0 = ((const float4*)(g_W + (size_t)b0 * DIM))[lane];
    } else {
        a0 = make_float4(0.f, 0.f, 0.f, 0.f);
#pragma unroll
        for (int j = 0; j < 4; ++j) {
            const int node = __ldg(left_common + __shfl_sync(0xffffffffu, ridx_l, j));
            const float4 v = __ldg((const float4*)(out + (size_t)node * DIM) + lane);
            a0.x += v.x; a0.y += v.y; a0.z += v.z; a0.w += v.w;
        }
    }
    if (two) {
        if (ok1) {
            a1 = ((const float4*)(g_W + (size_t)b1 * DIM))[lane];
        } else {
            a1 = make_float4(0.f, 0.f, 0.f, 0.f);
#pragma unroll
            for (int j = 0; j < 4; ++j) {
                const int node = __ldg(left_common + __shfl_sync(0xffffffffu, ridx_l, 4 + j));
                const float4 v = __ldg((const float4*)(out + (size_t)node * DIM) + lane);
                a1.x += v.x; a1.y += v.y; a1.z += v.z; a1.w += v.w;
            }
        }
    }

    const float addc = (float)(n_typ - 4);
    const float inv  = 0.2f;

    float4 o0;
    o0.x = e0.x * (1.0f - (a0.x + addc) * inv);
    o0.y = e0.y * (1.0f - (a0.y + addc) * inv);
    o0.z = e0.z * (1.0f - (a0.z + addc) * inv);
    o0.w = e0.w * (1.0f - (a0.w + addc) * inv);
    __stcs((float4*)(out + (size_t)rs0 * DIM) + lane, o0);

    if (two) {
        float4 o1;
        o1.x = e1.x * (1.0f - (a1.x + addc) * inv);
        o1.y = e1.y * (1.0f - (a1.y + addc) * inv);
        o1.z = e1.z * (1.0f - (a1.z + addc) * inv);
        o1.w = e1.w * (1.0f - (a1.w + addc) * inv);
        __stcs((float4*)(out + (size_t)rs1 * DIM) + lane, o1);
    }
}

// Generic fallback (any deg3), one warp per entity.
__global__ void sub3_kernel_gen(const float* __restrict__ emb,
                                const int* __restrict__ sub3_row,
                                const int* __restrict__ left_common,
                                const int* __restrict__ right_specific,
                                float* out,
                                int n_ent, int n_typ, int deg3) {
    const int gw   = (int)((blockIdx.x * (size_t)blockDim.x + threadIdx.x) >> 5);
    const int lane = threadIdx.x & 31;
    if (gw >= n_ent) return;

    const float addc = (float)(n_typ - deg3);
    const float inv  = 1.0f / (float)(1 + deg3);

    float4 acc = make_float4(0.f, 0.f, 0.f, 0.f);
    const int* rbase = sub3_row + (size_t)gw * deg3;
    for (int j = 0; j < deg3; ++j) {
        const int node = left_common[__ldg(rbase + j)];
        const float4 v = __ldg((const float4*)(out + (size_t)node * DIM) + lane);
        acc.x += v.x; acc.y += v.y; acc.z += v.z; acc.w += v.w;
    }
    const int   rs = right_specific[gw];
    const float4 e = __ldcs((const float4*)(emb + (size_t)rs * DIM) + lane);
    float4 r;
    r.x = e.x * (1.0f - (acc.x + addc) * inv);
    r.y = e.y * (1.0f - (acc.y + addc) * inv);
    r.z = e.z * (1.0f - (acc.z + addc) * inv);
    r.w = e.w * (1.0f - (acc.w + addc) * inv);
    __stcs((float4*)(out + (size_t)rs * DIM) + lane, r);
}

extern "C" void kernel_launch(void* const* d_in, const int* in_sizes, int n_in,
                              void* d_out, int out_size) {
    const float* emb            = (const float*)d_in[0];
    const int*   sub2_row       = (const int*)d_in[1];
    const int*   sub3_row       = (const int*)d_in[3];
    const int*   left_specific  = (const int*)d_in[5];
    const int*   right_common   = (const int*)d_in[6];
    const int*   left_common    = (const int*)d_in[7];
    const int*   right_specific = (const int*)d_in[8];
    float*       out            = (float*)d_out;

    const int n_ent = in_sizes[5];                 // 200000
    const int n_typ = in_sizes[7];                 // 1000
    const int deg2  = in_sizes[1] / n_typ;         // 64
    const int deg3  = in_sizes[3] / n_ent;         // 4

    // Phase 1: updated type rows -> out[type rows]
    if (deg2 == 64) {
        sub2_kernel_u8<<<n_typ, 256>>>(
            emb, sub2_row, left_specific, right_common, out, n_ent, deg2);
    } else {
        const int smem = ((deg2 * 4 + 127) & ~127) + 8 * 32 * (int)sizeof(float4);
        sub2_kernel<<<n_typ, 256, smem>>>(
            emb, sub2_row, left_specific, right_common, out, n_ent, deg2);
    }

    if (deg3 == 4 && n_typ <= MAX_TYP) {
        window_kernel<<<(n_typ + 3) / 4, 128>>>(out, left_common, n_typ);
        const int ent_per_block = 8 * 2;
        const int blocks = (n_ent + ent_per_block - 1) / ent_per_block;
        sub3_kernel_d2w<<<blocks, 256>>>(
            emb, sub3_row, left_common, right_specific, out, n_ent, n_typ);
    } else {
        const int wpb = 8;
        const int blocks = (n_ent + wpb - 1) / wpb;
        sub3_kernel_gen<<<blocks, wpb * 32>>>(
            emb, sub3_row, left_common, right_specific, out, n_ent, n_typ, deg3);
    }
}